// round 4
// baseline (speedup 1.0000x reference)
#include <cuda_runtime.h>
#include <math.h>

#define TTOK 8192
#define DM   1024
#define DFF  4096
#define NE   8

#define BM 128
#define BN 64
#define BK 16

// ---------------- scratch (static device globals: allowed) ----------------
__device__ int   g_counts[NE];
__device__ int   g_pair[NE][TTOK];     // pair id = token*2 + slot
__device__ float g_wt[NE][TTOK];       // combine weight for that pair
__device__ float g_H[(size_t)2 * TTOK * DFF];  // 256 MB intermediate
__device__ float g_Y[(size_t)2 * TTOK * DM];   // 64 MB per-pair outputs

// ---------------- init: reset per-launch state ----------------
__global__ void k_init() {
    if (threadIdx.x < NE) g_counts[threadIdx.x] = 0;
}

// ---------------- router: one warp per token ----------------
__global__ void k_router(const float* __restrict__ x,
                         const float* __restrict__ gW,
                         const float* __restrict__ gb) {
    int t    = (blockIdx.x * blockDim.x + threadIdx.x) >> 5;
    int lane = threadIdx.x & 31;
    if (t >= TTOK) return;
    const float* xr = x + (size_t)t * DM;

    float acc[NE];
#pragma unroll
    for (int e = 0; e < NE; e++) acc[e] = 0.f;

    for (int i = lane; i < DM; i += 32) {
        float xv = xr[i];
#pragma unroll
        for (int e = 0; e < NE; e++) acc[e] += xv * gW[e * DM + i];
    }
#pragma unroll
    for (int e = 0; e < NE; e++) {
#pragma unroll
        for (int o = 16; o > 0; o >>= 1)
            acc[e] += __shfl_down_sync(0xffffffffu, acc[e], o);
    }
    if (lane == 0) {
        float best = -1e30f, sec = -1e30f;
        int b0 = 0, b1 = 0;
#pragma unroll
        for (int e = 0; e < NE; e++) {
            float l = acc[e] + gb[e];
            if (l > best)      { sec = best; b1 = b0; best = l; b0 = e; }
            else if (l > sec)  { sec = l; b1 = e; }
        }
        float ex = expf(sec - best);       // softmax over top-2
        float inv = 1.f / (1.f + ex);
        float w0 = inv, w1 = ex * inv;
        int i0 = atomicAdd(&g_counts[b0], 1);
        g_pair[b0][i0] = t * 2;     g_wt[b0][i0] = w0;
        int i1 = atomicAdd(&g_counts[b1], 1);
        g_pair[b1][i1] = t * 2 + 1; g_wt[b1][i1] = w1;
    }
}

// ---------------- grouped GEMM 1: H = silu(X Wg^T) * (X W1^T) ----------------
// grid: (DFF/BN, TTOK/BM, NE). block 256 threads, 8x4 thread tile, dual accum.
__global__ __launch_bounds__(256)
void k_ffn1(const float* __restrict__ x,
            const float* __restrict__ Wg,
            const float* __restrict__ W1) {
    int e   = blockIdx.z;
    int cnt = g_counts[e];
    int m0  = blockIdx.y * BM;
    if (m0 >= cnt) return;
    int n0  = blockIdx.x * BN;

    __shared__ float sA[BK][BM + 4];
    __shared__ float sG[BK][BN + 4];
    __shared__ float sV[BK][BN + 4];
    __shared__ int   sPair[BM];

    int tid = threadIdx.x;
    if (tid < BM) {
        int r  = m0 + tid;
        int rr = r < cnt ? r : cnt - 1;
        sPair[tid] = g_pair[e][rr];
    }
    __syncthreads();

    const float* Bg = Wg + (size_t)e * DFF * DM + (size_t)n0 * DM;
    const float* Bv = W1 + (size_t)e * DFF * DM + (size_t)n0 * DM;

    int tcol = (tid & 15) * 4;   // 0..60
    int trow = (tid >> 4) * 8;   // 0..120

    float accG[8][4], accV[8][4];
#pragma unroll
    for (int i = 0; i < 8; i++)
#pragma unroll
        for (int j = 0; j < 4; j++) { accG[i][j] = 0.f; accV[i][j] = 0.f; }

    // precompute this thread's A-load rows (2 float4s per chunk)
    int am0 = tid >> 2;            int ak0 = (tid & 3) * 4;
    int am1 = (tid + 256) >> 2;    int ak1 = ak0;  // same (f&3) pattern
    const float* arow0 = x + (size_t)(sPair[am0] >> 1) * DM;
    const float* arow1 = x + (size_t)(sPair[am1] >> 1) * DM;
    int bn = tid >> 2;             int bk = (tid & 3) * 4;
    const float* bgrow = Bg + (size_t)bn * DM;
    const float* bvrow = Bv + (size_t)bn * DM;

    for (int k0 = 0; k0 < DM; k0 += BK) {
        float4 a0 = *(const float4*)(arow0 + k0 + ak0);
        float4 a1 = *(const float4*)(arow1 + k0 + ak1);
        float4 bg = *(const float4*)(bgrow + k0 + bk);
        float4 bv = *(const float4*)(bvrow + k0 + bk);
        sA[ak0 + 0][am0] = a0.x; sA[ak0 + 1][am0] = a0.y;
        sA[ak0 + 2][am0] = a0.z; sA[ak0 + 3][am0] = a0.w;
        sA[ak1 + 0][am1] = a1.x; sA[ak1 + 1][am1] = a1.y;
        sA[ak1 + 2][am1] = a1.z; sA[ak1 + 3][am1] = a1.w;
        sG[bk + 0][bn] = bg.x; sG[bk + 1][bn] = bg.y;
        sG[bk + 2][bn] = bg.z; sG[bk + 3][bn] = bg.w;
        sV[bk + 0][bn] = bv.x; sV[bk + 1][bn] = bv.y;
        sV[bk + 2][bn] = bv.z; sV[bk + 3][bn] = bv.w;
        __syncthreads();

#pragma unroll
        for (int kk = 0; kk < BK; kk++) {
            float a[8];
            *(float4*)&a[0] = *(const float4*)&sA[kk][trow];
            *(float4*)&a[4] = *(const float4*)&sA[kk][trow + 4];
            float bgf[4]; *(float4*)bgf = *(const float4*)&sG[kk][tcol];
            float bvf[4]; *(float4*)bvf = *(const float4*)&sV[kk][tcol];
#pragma unroll
            for (int i = 0; i < 8; i++)
#pragma unroll
                for (int j = 0; j < 4; j++) {
                    accG[i][j] += a[i] * bgf[j];
                    accV[i][j] += a[i] * bvf[j];
                }
        }
        __syncthreads();
    }

    // epilogue: H = silu(G) * V
#pragma unroll
    for (int i = 0; i < 8; i++) {
        int r = m0 + trow + i;
        if (r < cnt) {
            int pair = sPair[trow + i];
            float4 hv;
            float g0 = accG[i][0]; hv.x = (g0 / (1.f + expf(-g0))) * accV[i][0];
            float g1 = accG[i][1]; hv.y = (g1 / (1.f + expf(-g1))) * accV[i][1];
            float g2 = accG[i][2]; hv.z = (g2 / (1.f + expf(-g2))) * accV[i][2];
            float g3 = accG[i][3]; hv.w = (g3 / (1.f + expf(-g3))) * accV[i][3];
            *(float4*)(g_H + (size_t)pair * DFF + n0 + tcol) = hv;
        }
    }
}

// ---------------- grouped GEMM 2: Y = (H @ W2^T) * w ----------------
// grid: (DM/BN, TTOK/BM, NE)
__global__ __launch_bounds__(256)
void k_ffn2(const float* __restrict__ W2) {
    int e   = blockIdx.z;
    int cnt = g_counts[e];
    int m0  = blockIdx.y * BM;
    if (m0 >= cnt) return;
    int n0  = blockIdx.x * BN;

    __shared__ float sA[BK][BM + 4];
    __shared__ float sB[BK][BN + 4];
    __shared__ int   sPair[BM];

    int tid = threadIdx.x;
    if (tid < BM) {
        int r  = m0 + tid;
        int rr = r < cnt ? r : cnt - 1;
        sPair[tid] = g_pair[e][rr];
    }
    __syncthreads();

    const float* B = W2 + (size_t)e * DM * DFF + (size_t)n0 * DFF;

    int tcol = (tid & 15) * 4;
    int trow = (tid >> 4) * 8;

    float acc[8][4];
#pragma unroll
    for (int i = 0; i < 8; i++)
#pragma unroll
        for (int j = 0; j < 4; j++) acc[i][j] = 0.f;

    int am0 = tid >> 2;          int ak0 = (tid & 3) * 4;
    int am1 = (tid + 256) >> 2;
    const float* arow0 = g_H + (size_t)sPair[am0] * DFF;
    const float* arow1 = g_H + (size_t)sPair[am1] * DFF;
    int bn = tid >> 2;           int bk = (tid & 3) * 4;
    const float* brow = B + (size_t)bn * DFF;

    for (int k0 = 0; k0 < DFF; k0 += BK) {
        float4 a0 = *(const float4*)(arow0 + k0 + ak0);
        float4 a1 = *(const float4*)(arow1 + k0 + ak0);
        float4 b4 = *(const float4*)(brow + k0 + bk);
        sA[ak0 + 0][am0] = a0.x; sA[ak0 + 1][am0] = a0.y;
        sA[ak0 + 2][am0] = a0.z; sA[ak0 + 3][am0] = a0.w;
        sA[ak0 + 0][am1] = a1.x; sA[ak0 + 1][am1] = a1.y;
        sA[ak0 + 2][am1] = a1.z; sA[ak0 + 3][am1] = a1.w;
        sB[bk + 0][bn] = b4.x; sB[bk + 1][bn] = b4.y;
        sB[bk + 2][bn] = b4.z; sB[bk + 3][bn] = b4.w;
        __syncthreads();

#pragma unroll
        for (int kk = 0; kk < BK; kk++) {
            float a[8];
            *(float4*)&a[0] = *(const float4*)&sA[kk][trow];
            *(float4*)&a[4] = *(const float4*)&sA[kk][trow + 4];
            float bf[4]; *(float4*)bf = *(const float4*)&sB[kk][tcol];
#pragma unroll
            for (int i = 0; i < 8; i++)
#pragma unroll
                for (int j = 0; j < 4; j++) acc[i][j] += a[i] * bf[j];
        }
        __syncthreads();
    }

#pragma unroll
    for (int i = 0; i < 8; i++) {
        int r = m0 + trow + i;
        if (r < cnt) {
            int   pair = sPair[trow + i];
            float w    = g_wt[e][r];
            float4 yv;
            yv.x = acc[i][0] * w; yv.y = acc[i][1] * w;
            yv.z = acc[i][2] * w; yv.w = acc[i][3] * w;
            *(float4*)(g_Y + (size_t)pair * DM + n0 + tcol) = yv;
        }
    }
}

// ---------------- combine: out[t] = Y[2t] + Y[2t+1] ----------------
__global__ void k_combine(float* __restrict__ out) {
    size_t i = (size_t)blockIdx.x * blockDim.x + threadIdx.x;  // over T*DM/4
    const float4* y = (const float4*)g_Y;
    int t = (int)(i >> 8);          // DM/4 = 256 vec elems per row
    int j = (int)(i & 255);
    float4 a = y[(size_t)(2 * t) * 256 + j];
    float4 b = y[(size_t)(2 * t + 1) * 256 + j];
    float4 o;
    o.x = a.x + b.x; o.y = a.y + b.y; o.z = a.z + b.z; o.w = a.w + b.w;
    ((float4*)out)[i] = o;
}

// ---------------- launch ----------------
extern "C" void kernel_launch(void* const* d_in, const int* in_sizes, int n_in,
                              void* d_out, int out_size) {
    const float* x  = (const float*)d_in[0];
    const float* gW = (const float*)d_in[1];
    const float* gb = (const float*)d_in[2];
    const float* Wg = (const float*)d_in[3];
    const float* W1 = (const float*)d_in[4];
    const float* W2 = (const float*)d_in[5];
    float* out = (float*)d_out;

    k_init<<<1, 32>>>();
    k_router<<<TTOK / 8, 256>>>(x, gW, gb);   // 8 warps/block -> 8 tokens/block

    dim3 g1(DFF / BN, TTOK / BM, NE);
    k_ffn1<<<g1, 256>>>(x, Wg, W1);

    dim3 g2(DM / BN, TTOK / BM, NE);
    k_ffn2<<<g2, 256>>>(W2);

    k_combine<<<(TTOK * (DM / 4)) / 256, 256>>>(out);
}

// round 10
// speedup vs baseline: 2.2938x; 2.2938x over previous
#include <cuda_runtime.h>
#include <cuda_bf16.h>
#include <cstdint>
#include <math.h>

#define TTOK 8192
#define DM   1024
#define DFF  4096
#define NE   8
#define BM   128

// smem tile geometry: 128 rows x 32 bf16 (64B data), row stride 80B (20 words
// -> conflict-free fragment access). 4 tiles/stage (Ah,Al,Bh,Bl), 2 stages.
#define TILE_B   10240       // 128 * 80
#define STAGE_B  40960       // 4 * TILE_B
#define SMEM_DYN (2 * STAGE_B)

// ---------------- device scratch ----------------
__device__ int   g_counts[NE];
__device__ int   g_pair[NE][TTOK];
__device__ float g_wt[NE][TTOK];
__device__ __nv_bfloat16 g_xh[(size_t)TTOK * DM],        g_xl[(size_t)TTOK * DM];
__device__ __nv_bfloat16 g_Wgh[(size_t)NE * DFF * DM],   g_Wgl[(size_t)NE * DFF * DM];
__device__ __nv_bfloat16 g_W1h[(size_t)NE * DFF * DM],   g_W1l[(size_t)NE * DFF * DM];
__device__ __nv_bfloat16 g_W2h[(size_t)NE * DM * DFF],   g_W2l[(size_t)NE * DM * DFF];
__device__ __nv_bfloat16 g_Hh[(size_t)2 * TTOK * DFF],   g_Hl[(size_t)2 * TTOK * DFF];
__device__ float g_Y[(size_t)2 * TTOK * DM];

// ---------------- helpers ----------------
__device__ __forceinline__ uint32_t smem_u32(const void* p) {
    uint32_t a;
    asm("{ .reg .u64 t; cvta.to.shared.u64 t, %1; cvt.u32.u64 %0, t; }" : "=r"(a) : "l"(p));
    return a;
}
__device__ __forceinline__ uint32_t lds32(uint32_t a) {
    uint32_t v;
    asm volatile("ld.shared.b32 %0, [%1];" : "=r"(v) : "r"(a));
    return v;
}
__device__ __forceinline__ void mma16816(float* d, const uint32_t* A, uint32_t b0, uint32_t b1) {
    asm volatile(
        "mma.sync.aligned.m16n8k16.row.col.f32.bf16.bf16.f32 "
        "{%0,%1,%2,%3}, {%4,%5,%6,%7}, {%8,%9}, {%0,%1,%2,%3};"
        : "+f"(d[0]), "+f"(d[1]), "+f"(d[2]), "+f"(d[3])
        : "r"(A[0]), "r"(A[1]), "r"(A[2]), "r"(A[3]), "r"(b0), "r"(b1));
}
#define CP16(dst, src) asm volatile("cp.async.cg.shared.global [%0], [%1], 16;" :: "r"(dst), "l"(src) : "memory")
#define CP_COMMIT()    asm volatile("cp.async.commit_group;" ::: "memory")
#define CP_WAIT1()     asm volatile("cp.async.wait_group 1;" ::: "memory")
#define CP_WAIT0()     asm volatile("cp.async.wait_group 0;" ::: "memory")

// 3-pass hi/lo compute on one K-chunk (32 bf16). Tiles at st+0:Ah, +TILE_B:Al,
// +2*TILE_B:Bh, +3*TILE_B:Bl. Warp tile 32(m) x 64(n).
__device__ __forceinline__ void compute_chunk(uint32_t st, int warp_m, int warp_n,
                                              int group, int tq, float acc[2][8][4]) {
#pragma unroll
    for (int pass = 0; pass < 3; pass++) {
        uint32_t ab = st + (pass == 2 ? TILE_B : 0);
        uint32_t bb = st + (pass == 1 ? 3 * TILE_B : 2 * TILE_B);
#pragma unroll
        for (int ks = 0; ks < 2; ks++) {
            int kb = ks * 16;
            uint32_t A[2][4];
#pragma unroll
            for (int mf = 0; mf < 2; mf++) {
                uint32_t ad = ab + (uint32_t)(warp_m * 32 + mf * 16 + group) * 80
                                 + (uint32_t)(kb + tq * 2) * 2;
                A[mf][0] = lds32(ad);        // (r,   k)
                A[mf][1] = lds32(ad + 640);  // (r+8, k)
                A[mf][2] = lds32(ad + 16);   // (r,   k+8)
                A[mf][3] = lds32(ad + 656);  // (r+8, k+8)
            }
#pragma unroll
            for (int nf = 0; nf < 8; nf++) {
                uint32_t bd = bb + (uint32_t)(warp_n * 64 + nf * 8 + group) * 80
                                 + (uint32_t)(kb + tq * 2) * 2;
                uint32_t b0 = lds32(bd), b1 = lds32(bd + 16);
                mma16816(acc[0][nf], A[0], b0, b1);
                mma16816(acc[1][nf], A[1], b0, b1);
            }
        }
    }
}

// stage loader: sPtr[tile][row] -> row base pointer; k-chunk c
#define LOADC(c) do { \
    uint32_t st_ = sb + (uint32_t)(((c) & 1) * STAGE_B); \
    int kof_ = (c) * 32; \
    _Pragma("unroll") \
    for (int j_ = 0; j_ < 8; j_++) { \
        int i_ = tid + 256 * j_; \
        int tile_ = i_ >> 9; int row_ = (i_ >> 2) & 127; int seg_ = i_ & 3; \
        uint32_t dst_ = st_ + (uint32_t)(tile_ * TILE_B + row_ * 80 + seg_ * 16); \
        const __nv_bfloat16* src_ = sPtr[tile_][row_] + kof_ + seg_ * 8; \
        CP16(dst_, src_); \
    } \
    CP_COMMIT(); } while (0)

// ---------------- init / router ----------------
__global__ void k_init() { if (threadIdx.x < NE) g_counts[threadIdx.x] = 0; }

__global__ void k_router(const float* __restrict__ x, const float* __restrict__ gW,
                         const float* __restrict__ gb) {
    int t = (blockIdx.x * blockDim.x + threadIdx.x) >> 5;
    int lane = threadIdx.x & 31;
    if (t >= TTOK) return;
    const float* xr = x + (size_t)t * DM;
    float acc[NE];
#pragma unroll
    for (int e = 0; e < NE; e++) acc[e] = 0.f;
    for (int i = lane; i < DM; i += 32) {
        float xv = xr[i];
#pragma unroll
        for (int e = 0; e < NE; e++) acc[e] += xv * gW[e * DM + i];
    }
#pragma unroll
    for (int e = 0; e < NE; e++)
#pragma unroll
        for (int o = 16; o > 0; o >>= 1) acc[e] += __shfl_down_sync(0xffffffffu, acc[e], o);
    if (lane == 0) {
        float best = -1e30f, sec = -1e30f; int b0 = 0, b1 = 0;
#pragma unroll
        for (int e = 0; e < NE; e++) {
            float l = acc[e] + gb[e];
            if (l > best) { sec = best; b1 = b0; best = l; b0 = e; }
            else if (l > sec) { sec = l; b1 = e; }
        }
        float ex = expf(sec - best);
        float inv = 1.f / (1.f + ex);
        int i0 = atomicAdd(&g_counts[b0], 1);
        g_pair[b0][i0] = t * 2;     g_wt[b0][i0] = inv;
        int i1 = atomicAdd(&g_counts[b1], 1);
        g_pair[b1][i1] = t * 2 + 1; g_wt[b1][i1] = ex * inv;
    }
}

// ---------------- fp32 -> bf16 hi/lo split ----------------
// which: 0=x, 1=Wg, 2=W1, 3=W2. Destination pointers resolved in DEVICE code
// (passing __device__ globals as kernel args from host passes the host shadow
// symbol address -> garbage; that was the round-9 bug).
__global__ void k_split(const float4* __restrict__ in, int which, int n4) {
    int i = blockIdx.x * blockDim.x + threadIdx.x;
    if (i >= n4) return;
    __nv_bfloat16 *hi, *lo;
    switch (which) {
        case 0:  hi = g_xh;  lo = g_xl;  break;
        case 1:  hi = g_Wgh; lo = g_Wgl; break;
        case 2:  hi = g_W1h; lo = g_W1l; break;
        default: hi = g_W2h; lo = g_W2l; break;
    }
    float4 v = in[i];
    __nv_bfloat16 h0 = __float2bfloat16(v.x), h1 = __float2bfloat16(v.y);
    __nv_bfloat16 h2 = __float2bfloat16(v.z), h3 = __float2bfloat16(v.w);
    __nv_bfloat162* H = (__nv_bfloat162*)hi;
    __nv_bfloat162* L = (__nv_bfloat162*)lo;
    H[2 * i]     = __nv_bfloat162(h0, h1);
    H[2 * i + 1] = __nv_bfloat162(h2, h3);
    L[2 * i]     = __nv_bfloat162(__float2bfloat16(v.x - __bfloat162float(h0)),
                                  __float2bfloat16(v.y - __bfloat162float(h1)));
    L[2 * i + 1] = __nv_bfloat162(__float2bfloat16(v.z - __bfloat162float(h2)),
                                  __float2bfloat16(v.w - __bfloat162float(h3)));
}

// ---------------- GEMM1: C=[G|V] = X @ [Wg_n|W1_n]^T, SwiGLU epilogue ----------------
// grid (DFF/64, TTOK/BM, NE). n0 covers 64 output cols of both G and V.
#define NC1 (DM / 32)   // 32
__global__ __launch_bounds__(256)
void k_mma1() {
    int e = blockIdx.z;
    int cnt = g_counts[e];
    int m0 = blockIdx.y * BM;
    if (m0 >= cnt) return;
    int n0 = blockIdx.x * 64;

    extern __shared__ char dsm[];
    __shared__ int sPair[BM];
    __shared__ const __nv_bfloat16* sPtr[4][BM];

    int tid = threadIdx.x, wid = tid >> 5, lane = tid & 31;
    int warp_m = wid & 3, warp_n = wid >> 2;
    int group = lane >> 2, tq = lane & 3;
    uint32_t sb = smem_u32(dsm);

    if (tid < BM) {
        int r = m0 + tid;
        int p = g_pair[e][r < cnt ? r : cnt - 1];
        sPair[tid] = p;
        size_t tok = (size_t)(p >> 1) * DM;
        sPtr[0][tid] = g_xh + tok;
        sPtr[1][tid] = g_xl + tok;
        size_t eo = (size_t)e * DFF * DM;
        sPtr[2][tid] = (tid < 64) ? g_Wgh + eo + (size_t)(n0 + tid) * DM
                                  : g_W1h + eo + (size_t)(n0 + tid - 64) * DM;
        sPtr[3][tid] = (tid < 64) ? g_Wgl + eo + (size_t)(n0 + tid) * DM
                                  : g_W1l + eo + (size_t)(n0 + tid - 64) * DM;
    }
    __syncthreads();

    float acc[2][8][4];
#pragma unroll
    for (int a = 0; a < 2; a++)
#pragma unroll
        for (int b = 0; b < 8; b++)
#pragma unroll
            for (int c = 0; c < 4; c++) acc[a][b][c] = 0.f;

    LOADC(0); LOADC(1);
    for (int c = 0; c < NC1; c++) {
        if (c < NC1 - 1) CP_WAIT1(); else CP_WAIT0();
        __syncthreads();
        compute_chunk(sb + (uint32_t)((c & 1) * STAGE_B), warp_m, warp_n, group, tq, acc);
        __syncthreads();
        if (c + 2 < NC1) LOADC(c + 2);
    }

    // stage C through smem (reuse pipeline buffers), combine G/V -> H hi/lo
    float* sC = (float*)dsm;  // [128][132]
#pragma unroll
    for (int mf = 0; mf < 2; mf++)
#pragma unroll
        for (int nf = 0; nf < 8; nf++) {
            int r = warp_m * 32 + mf * 16 + group;
            int col = warp_n * 64 + nf * 8 + tq * 2;
            *(float2*)&sC[r * 132 + col]       = make_float2(acc[mf][nf][0], acc[mf][nf][1]);
            *(float2*)&sC[(r + 8) * 132 + col] = make_float2(acc[mf][nf][2], acc[mf][nf][3]);
        }
    __syncthreads();

    int row = tid >> 1, half = tid & 1;
    if (m0 + row < cnt) {
        int pair = sPair[row];
        const float* cg = sC + row * 132 + half * 32;
        const float* cv = cg + 64;
        uint32_t hh[16], hl[16];
#pragma unroll
        for (int j = 0; j < 16; j++) {
            float g0 = cg[2 * j], g1 = cg[2 * j + 1];
            float v0 = cv[2 * j], v1 = cv[2 * j + 1];
            float h0 = g0 / (1.f + __expf(-g0)) * v0;
            float h1 = g1 / (1.f + __expf(-g1)) * v1;
            __nv_bfloat16 b0 = __float2bfloat16(h0), b1 = __float2bfloat16(h1);
            __nv_bfloat162 hi2(b0, b1);
            __nv_bfloat162 lo2(__float2bfloat16(h0 - __bfloat162float(b0)),
                               __float2bfloat16(h1 - __bfloat162float(b1)));
            hh[j] = *(uint32_t*)&hi2;
            hl[j] = *(uint32_t*)&lo2;
        }
        uint4* dh = (uint4*)(g_Hh + (size_t)pair * DFF + n0 + half * 32);
        uint4* dl = (uint4*)(g_Hl + (size_t)pair * DFF + n0 + half * 32);
#pragma unroll
        for (int q = 0; q < 4; q++) { dh[q] = ((uint4*)hh)[q]; dl[q] = ((uint4*)hl)[q]; }
    }
}

// ---------------- GEMM2: Y = (H @ W2^T) * w ----------------
// grid (DM/128, TTOK/BM, NE)
#define NC2 (DFF / 32)  // 128
__global__ __launch_bounds__(256)
void k_mma2() {
    int e = blockIdx.z;
    int cnt = g_counts[e];
    int m0 = blockIdx.y * BM;
    if (m0 >= cnt) return;
    int n0 = blockIdx.x * 128;

    extern __shared__ char dsm[];
    __shared__ int sPair[BM];
    __shared__ float sWt[BM];
    __shared__ const __nv_bfloat16* sPtr[4][BM];

    int tid = threadIdx.x, wid = tid >> 5, lane = tid & 31;
    int warp_m = wid & 3, warp_n = wid >> 2;
    int group = lane >> 2, tq = lane & 3;
    uint32_t sb = smem_u32(dsm);

    if (tid < BM) {
        int r = m0 + tid;
        int rr = r < cnt ? r : cnt - 1;
        int p = g_pair[e][rr];
        sPair[tid] = p;
        sWt[tid] = g_wt[e][rr];
        size_t po = (size_t)p * DFF;
        sPtr[0][tid] = g_Hh + po;
        sPtr[1][tid] = g_Hl + po;
        size_t eo = (size_t)e * DM * DFF;
        sPtr[2][tid] = g_W2h + eo + (size_t)(n0 + tid) * DFF;
        sPtr[3][tid] = g_W2l + eo + (size_t)(n0 + tid) * DFF;
    }
    __syncthreads();

    float acc[2][8][4];
#pragma unroll
    for (int a = 0; a < 2; a++)
#pragma unroll
        for (int b = 0; b < 8; b++)
#pragma unroll
            for (int c = 0; c < 4; c++) acc[a][b][c] = 0.f;

    LOADC(0); LOADC(1);
    for (int c = 0; c < NC2; c++) {
        if (c < NC2 - 1) CP_WAIT1(); else CP_WAIT0();
        __syncthreads();
        compute_chunk(sb + (uint32_t)((c & 1) * STAGE_B), warp_m, warp_n, group, tq, acc);
        __syncthreads();
        if (c + 2 < NC2) LOADC(c + 2);
    }

    // epilogue: scale by combine weight, write per-pair rows
#pragma unroll
    for (int mf = 0; mf < 2; mf++)
#pragma unroll
        for (int sub = 0; sub < 2; sub++) {
            int r = warp_m * 32 + mf * 16 + group + sub * 8;
            if (m0 + r < cnt) {
                float w = sWt[r];
                float* Y = g_Y + (size_t)sPair[r] * DM + n0;
#pragma unroll
                for (int nf = 0; nf < 8; nf++) {
                    int col = warp_n * 64 + nf * 8 + tq * 2;
                    float2 v = make_float2(acc[mf][nf][sub * 2] * w,
                                           acc[mf][nf][sub * 2 + 1] * w);
                    *(float2*)(Y + col) = v;
                }
            }
        }
}

// ---------------- combine ----------------
__global__ void k_combine(float* __restrict__ out) {
    size_t i = (size_t)blockIdx.x * blockDim.x + threadIdx.x;
    const float4* y = (const float4*)g_Y;
    int t = (int)(i >> 8);
    int j = (int)(i & 255);
    float4 a = y[(size_t)(2 * t) * 256 + j];
    float4 b = y[(size_t)(2 * t + 1) * 256 + j];
    float4 o;
    o.x = a.x + b.x; o.y = a.y + b.y; o.z = a.z + b.z; o.w = a.w + b.w;
    ((float4*)out)[i] = o;
}

// ---------------- launch ----------------
extern "C" void kernel_launch(void* const* d_in, const int* in_sizes, int n_in,
                              void* d_out, int out_size) {
    const float* x  = (const float*)d_in[0];
    const float* gW = (const float*)d_in[1];
    const float* gb = (const float*)d_in[2];
    const float* Wg = (const float*)d_in[3];
    const float* W1 = (const float*)d_in[4];
    const float* W2 = (const float*)d_in[5];
    float* out = (float*)d_out;

    cudaFuncSetAttribute(k_mma1, cudaFuncAttributeMaxDynamicSharedMemorySize, SMEM_DYN);
    cudaFuncSetAttribute(k_mma2, cudaFuncAttributeMaxDynamicSharedMemorySize, SMEM_DYN);

    k_init<<<1, 32>>>();
    k_router<<<TTOK / 8, 256>>>(x, gW, gb);

    int n4x = TTOK * DM / 4;
    k_split<<<(n4x + 255) / 256, 256>>>((const float4*)x, 0, n4x);
    int n4w = NE * DFF * DM / 4;
    k_split<<<(n4w + 255) / 256, 256>>>((const float4*)Wg, 1, n4w);
    k_split<<<(n4w + 255) / 256, 256>>>((const float4*)W1, 2, n4w);
    k_split<<<(n4w + 255) / 256, 256>>>((const float4*)W2, 3, n4w);

    dim3 g1(DFF / 64, TTOK / BM, NE);   // 64 x 64 x 8
    k_mma1<<<g1, 256, SMEM_DYN>>>();

    dim3 g2(DM / 128, TTOK / BM, NE);   // 8 x 64 x 8
    k_mma2<<<g2, 256, SMEM_DYN>>>();

    k_combine<<<(TTOK * (DM / 4)) / 256, 256>>>(out);
}